// round 9
// baseline (speedup 1.0000x reference)
#include <cuda_runtime.h>
#include <cstdint>

// Fixed problem: x [256,2048,7,7] fp32, x0 [256,49,1] fp32, out scalar fp32
#define BATCH   256
#define NQ      4                     // K-split partials per batch
#define NCTA    (BATCH * NQ)          // 1024
#define KQ      512                   // channels per CTA
#define KCH     64                    // channels per chunk
#define NCH     (KQ / KCH)            // 8
#define NDIM    49
#define PAIRS   32                    // KCH/2 packed k-pair rows per chunk
#define SROW    72                    // f16x2 words per row -> conflict-free frags
#define BUFW    (PAIRS * SROW)        // 2304 words per buffer
#define THREADS 128
#define EPSV    1e-12f

__device__ float g_partial[NCTA][NDIM * NDIM];
__device__ float g_penalty[BATCH];
__device__ int   g_cnt[BATCH];        // zero-init; reset each run
__device__ int   g_cnt_all;

// pack two fp32 channel values into f16x2 (hi = k odd, lo = k even)
static __device__ __forceinline__ uint32_t pack_h2(float k_odd, float k_even) {
    uint32_t d;
    asm("cvt.rn.f16x2.f32 %0, %1, %2;" : "=r"(d) : "f"(k_odd), "f"(k_even));
    return d;
}

// m16n8k16 f16 mma, fp32 accumulate (sm_80 PTX, valid on base sm_103)
static __device__ __forceinline__ void mma16(float* c,
    uint32_t a0, uint32_t a1, uint32_t a2, uint32_t a3,
    uint32_t b0, uint32_t b1)
{
    asm("mma.sync.aligned.m16n8k16.row.col.f32.f16.f16.f32 "
        "{%0,%1,%2,%3}, {%4,%5,%6,%7}, {%8,%9}, {%0,%1,%2,%3};"
        : "+f"(c[0]), "+f"(c[1]), "+f"(c[2]), "+f"(c[3])
        : "r"(a0), "r"(a1), "r"(a2), "r"(a3), "r"(b0), "r"(b1));
}

static __device__ __forceinline__ float warpsum(float v) {
    v += __shfl_xor_sync(0xffffffffu, v, 16);
    v += __shfl_xor_sync(0xffffffffu, v, 8);
    v += __shfl_xor_sync(0xffffffffu, v, 4);
    v += __shfl_xor_sync(0xffffffffu, v, 2);
    v += __shfl_xor_sync(0xffffffffu, v, 1);
    return v;
}

// dot(sA_row[0..48], sx[0..48]) with 4 accumulators
static __device__ __forceinline__ float dotrow(const float* __restrict__ row,
                                               const float* __restrict__ v) {
    float a0 = 0.f, a1 = 0.f, a2 = 0.f, a3 = 0.f;
#pragma unroll
    for (int m = 0; m < 48; m += 4) {
        a0 = fmaf(row[m + 0], v[m + 0], a0);
        a1 = fmaf(row[m + 1], v[m + 1], a1);
        a2 = fmaf(row[m + 2], v[m + 2], a2);
        a3 = fmaf(row[m + 3], v[m + 3], a3);
    }
    return (a0 + a1) + (a2 + a3) + row[48] * v[48];
}

// load + pack one 64-channel chunk; (r0,n0) = (t/49, t%49) precomputed.
// word w = t + 128*i -> pair-row r, col n; gmem pair = (2r*49+n, +49)
static __device__ __forceinline__ void load_pack(const float* __restrict__ src,
                                                 uint32_t* pre, int r0, int n0, int t) {
    int r = r0, n = n0;
#pragma unroll
    for (int i = 0; i < 12; i++) {
        const float* p = src + 98 * r + n;
        pre[i] = pack_h2(__ldg(p + NDIM), __ldg(p));
        n += 30; r += 2; if (n >= NDIM) { n -= NDIM; r += 1; }   // w += 128
    }
    if (t < 32) {                    // tail words 1536..1567 all in pair-row 31
        const float* p = src + 98 * 31 + 17 + t;
        pre[12] = pack_h2(__ldg(p + NDIM), __ldg(p));
    }
}

static __device__ __forceinline__ void store_pack(uint32_t* dst,
                                                  const uint32_t* pre, int r0, int n0, int t) {
    int r = r0, n = n0;
#pragma unroll
    for (int i = 0; i < 12; i++) {
        dst[r * SROW + n] = pre[i];
        n += 30; r += 2; if (n >= NDIM) { n -= NDIM; r += 1; }
    }
    if (t < 32) dst[31 * SROW + 17 + t] = pre[12];
}

__global__ void __launch_bounds__(THREADS, 5)
ofp_fused(const float* __restrict__ x, const float* __restrict__ x0,
          float* __restrict__ out)
{
    __shared__ uint32_t sbuf[2 * BUFW];      // 18432 B
    __shared__ float sA[NDIM * NDIM];        // Gram (also finalize staging)
    __shared__ float sx[64];
    __shared__ int scomm;

    const int t    = threadIdx.x;
    const int lane = t & 31, wid = t >> 5;
    const int l4   = lane & 3, ld4 = lane >> 2;
    const int cta  = blockIdx.x;
    const int b    = cta >> 2, q = cta & 3;
    const int qm   = wid >> 1, qn = wid & 1; // warp's 32x32 quadrant
    const int m0   = qm * 32 + ld4;
    const int n0f  = qn * 32 + ld4;
    const int r0   = t / NDIM;               // single division, chunk-invariant
    const int n0   = t - NDIM * r0;

    const float* __restrict__ xq =
        x + (size_t)b * (2048 * NDIM) + (size_t)q * (KQ * NDIM);

    // zero pad words n in [49,64) of both buffers (frags read n <= 63)
    for (int i = t; i < 2 * PAIRS * 15; i += THREADS) {
        const int bi  = i / (PAIRS * 15);
        const int rem = i - bi * (PAIRS * 15);
        const int r   = rem / 15;
        const int n   = NDIM + rem - r * 15;
        sbuf[bi * BUFW + r * SROW + n] = 0u;
    }

    float acc[2][4][4];
#pragma unroll
    for (int mt = 0; mt < 2; mt++)
#pragma unroll
        for (int nt = 0; nt < 4; nt++)
#pragma unroll
            for (int ci = 0; ci < 4; ci++) acc[mt][nt][ci] = 0.0f;

    // ---- prologue: c0 -> S0 ; c1 -> R1 ----
    uint32_t preA[13], preB[13];
    load_pack(xq, preA, r0, n0, t);
    store_pack(sbuf, preA, r0, n0, t);
    load_pack(xq + (size_t)(KCH * NDIM), preB, r0, n0, t);
    __syncthreads();

    // ---- main loop: distance-2 pipeline, 1 sync/iter ----
    // iter ch: load c(ch+2) -> R[ch&1]; MMA(S[ch&1]); store c(ch+1)=R[(ch+1)&1] -> S[(ch+1)&1]
    for (int ch = 0; ch < NCH; ch++) {
        uint32_t* rdst = (ch & 1) ? preB : preA;
        uint32_t* rsrc = (ch & 1) ? preA : preB;
        if (ch + 2 < NCH)
            load_pack(xq + (size_t)(ch + 2) * (KCH * NDIM), rdst, r0, n0, t);

        const uint32_t* bc = sbuf + (ch & 1) * BUFW;
#pragma unroll
        for (int kb = 0; kb < 4; kb++) {          // 4 k16 steps (8 pair-rows each)
            const uint32_t* lo = bc + (kb * 8 + l4) * SROW;
            const uint32_t* hi = lo + 4 * SROW;
            uint32_t b0[4], b1[4];
#pragma unroll
            for (int nt = 0; nt < 4; nt++) {
                b0[nt] = lo[n0f + nt * 8];
                b1[nt] = hi[n0f + nt * 8];
            }
#pragma unroll
            for (int mt = 0; mt < 2; mt++) {
                const uint32_t a0 = lo[m0 + mt * 16];
                const uint32_t a1 = lo[m0 + mt * 16 + 8];
                const uint32_t a2 = hi[m0 + mt * 16];
                const uint32_t a3 = hi[m0 + mt * 16 + 8];
#pragma unroll
                for (int nt = 0; nt < 4; nt++)
                    mma16(acc[mt][nt], a0, a1, a2, a3, b0[nt], b1[nt]);
            }
        }
        if (ch + 1 < NCH)
            store_pack(sbuf + ((ch + 1) & 1) * BUFW, rsrc, r0, n0, t);
        __syncthreads();
    }

    // ---- write 49x49 partial Gram ----
    {
        float* __restrict__ gp = g_partial[cta];
#pragma unroll
        for (int mt = 0; mt < 2; mt++)
#pragma unroll
            for (int nt = 0; nt < 4; nt++) {
                const int rr = qm * 32 + mt * 16 + ld4;
                const int cc = qn * 32 + nt * 8 + 2 * l4;
                const float* a = acc[mt][nt];
                if (rr < NDIM) {
                    if (cc < NDIM)     gp[rr * NDIM + cc]     = a[0];
                    if (cc + 1 < NDIM) gp[rr * NDIM + cc + 1] = a[1];
                }
                if (rr + 8 < NDIM) {
                    if (cc < NDIM)     gp[(rr + 8) * NDIM + cc]     = a[2];
                    if (cc + 1 < NDIM) gp[(rr + 8) * NDIM + cc + 1] = a[3];
                }
            }
    }
    __syncthreads();
    __threadfence();
    if (t == 0) scomm = atomicAdd(&g_cnt[b], 1);
    __syncthreads();
    if (scomm != NQ - 1) return;              // not the last partial of this batch

    // ================= last arriver: sum partials, then warp-0 PI =================
    __threadfence();
    {
        const float* __restrict__ p0 = g_partial[(b << 2) + 0];
        const float* __restrict__ p1 = g_partial[(b << 2) + 1];
        const float* __restrict__ p2 = g_partial[(b << 2) + 2];
        const float* __restrict__ p3 = g_partial[(b << 2) + 3];
        for (int i = t; i < NDIM * NDIM; i += THREADS)
            sA[i] = (__ldcg(p0 + i) + __ldcg(p1 + i)) +
                    (__ldcg(p2 + i) + __ldcg(p3 + i));
    }
    if (t < NDIM) sx[t] = x0[b * NDIM + t];
    __syncthreads();

    if (wid == 0) {
        const int  ra = lane, rb = lane + 32;
        const bool hasb = (lane < NDIM - 32);
        const float* rowA = &sA[ra * NDIM];
        const float* rowB = &sA[rb * NDIM];

        // PI-1: largest eigenvalue of ATA
        for (int it = 0; it < 9; it++) {
            const float y0 = dotrow(rowA, sx);
            const float y1 = hasb ? dotrow(rowB, sx) : 0.0f;
            const float n2 = warpsum(y0 * y0 + y1 * y1);
            const float inv = 1.0f / fmaxf(sqrtf(n2), EPSV);
            sx[ra] = y0 * inv;
            if (hasb) sx[rb] = y1 * inv;
            __syncwarp();
        }
        float x0v = sx[ra], x1v = hasb ? sx[rb] : 0.0f;
        float y0 = dotrow(rowA, sx);
        float y1 = hasb ? dotrow(rowB, sx) : 0.0f;
        float num = warpsum(y0 * x0v + y1 * x1v);
        float den = warpsum(x0v * x0v + x1v * x1v);
        const float largest = num / den;

        // PI-2 on (ATA - largest*I), warm-started from x1
        for (int it = 0; it < 9; it++) {
            const float y0s = dotrow(rowA, sx) - largest * sx[ra];
            const float y1s = hasb ? (dotrow(rowB, sx) - largest * sx[rb]) : 0.0f;
            const float n2 = warpsum(y0s * y0s + y1s * y1s);
            const float inv = 1.0f / fmaxf(sqrtf(n2), EPSV);
            sx[ra] = y0s * inv;
            if (hasb) sx[rb] = y1s * inv;
            __syncwarp();
        }
        x0v = sx[ra]; x1v = hasb ? sx[rb] : 0.0f;
        y0 = dotrow(rowA, sx) - largest * x0v;
        y1 = hasb ? (dotrow(rowB, sx) - largest * x1v) : 0.0f;
        num = warpsum(y0 * x0v + y1 * x1v);
        den = warpsum(x0v * x0v + x1v * x1v);
        const float smallest = (num / den) + largest;

        if (lane == 0) {
            const float r = largest / smallest - 1.0f;
            g_penalty[b] = r * r;             // BETA = 1
        }
    }
    __syncthreads();
    __threadfence();
    if (t == 0) scomm = atomicAdd(&g_cnt_all, 1);
    __syncthreads();
    if (scomm != BATCH - 1) return;           // not the global last batch

    // ================= global last arriver: deterministic finalize =================
    __threadfence();
    sA[t] = __ldcg(&g_penalty[t]) + __ldcg(&g_penalty[t + 128]);
    __syncthreads();
#pragma unroll
    for (int off = 64; off > 0; off >>= 1) {
        if (t < off) sA[t] += sA[t + off];
        __syncthreads();
    }
    if (t == 0) out[0] = sA[0] * (1.0f / (float)BATCH);

    // reset counters for the next graph replay
    g_cnt[t] = 0;
    g_cnt[t + 128] = 0;
    if (t == 0) g_cnt_all = 0;
}

extern "C" void kernel_launch(void* const* d_in, const int* in_sizes, int n_in,
                              void* d_out, int out_size) {
    const float* x  = (const float*)d_in[0];   // [256, 2048, 7, 7]
    const float* x0 = (const float*)d_in[1];   // [256, 49, 1]
    float* out = (float*)d_out;

    ofp_fused<<<NCTA, THREADS>>>(x, x0, out);
}

// round 10
// speedup vs baseline: 1.0035x; 1.0035x over previous
#include <cuda_runtime.h>
#include <cstdint>

// Fixed problem: x [256,2048,7,7] fp32, x0 [256,49,1] fp32, out scalar fp32
#define BATCH   256
#define NQ      4                     // K-split partials per batch
#define NCTA    (BATCH * NQ)          // 1024
#define KQ      512                   // channels per CTA
#define KCH     32                    // channels per stage
#define NST     (KQ / KCH)            // 16 stages
#define NDIM    49
#define SROW    72                    // words/row: (72k+n)%32 covers banks -> conflict-free frags
#define STW     (KCH * SROW)          // 2304 words per stage buffer
#define CHW     (KCH * NDIM)          // 1568 contiguous gmem floats per stage
#define STAGES  4
#define THREADS 128
#define EPSV    1e-12f

__device__ float g_partial[NCTA][NDIM * NDIM];
__device__ float g_penalty[BATCH];
__device__ int   g_cnt[BATCH];        // zero-init; reset each run
__device__ int   g_cnt_all;

#define CP_ASYNC4(dst, src) \
    asm volatile("cp.async.ca.shared.global [%0], [%1], 4;" :: "r"(dst), "l"(src))
#define CP_COMMIT() asm volatile("cp.async.commit_group;" ::: "memory")
#define CP_WAIT(n)  asm volatile("cp.async.wait_group %0;" :: "n"(n) : "memory")

// m16n8k8 tf32 mma on raw fp32 bits (HW truncates to tf32). sm_80 PTX.
static __device__ __forceinline__ void mma8(float* c,
    uint32_t a0, uint32_t a1, uint32_t a2, uint32_t a3,
    uint32_t b0, uint32_t b1)
{
    asm("mma.sync.aligned.m16n8k8.row.col.f32.tf32.tf32.f32 "
        "{%0,%1,%2,%3}, {%4,%5,%6,%7}, {%8,%9}, {%0,%1,%2,%3};"
        : "+f"(c[0]), "+f"(c[1]), "+f"(c[2]), "+f"(c[3])
        : "r"(a0), "r"(a1), "r"(a2), "r"(a3), "r"(b0), "r"(b1));
}

static __device__ __forceinline__ uint32_t smem_u32(const void* p) {
    uint32_t a;
    asm("{ .reg .u64 t; cvta.to.shared.u64 t, %1; cvt.u32.u64 %0, t; }" : "=r"(a) : "l"(p));
    return a;
}

// Block-wide sum over first 49 lanes' values (all 128 threads call).
static __device__ __forceinline__ float reduce49(float v, int t, float* sarr) {
    if (t < 64) sarr[t] = (t < NDIM) ? v : 0.0f;
    __syncthreads();
    if (t < 32) {
        float r = sarr[t] + sarr[t + 32];
        r += __shfl_xor_sync(0xffffffffu, r, 16);
        r += __shfl_xor_sync(0xffffffffu, r, 8);
        r += __shfl_xor_sync(0xffffffffu, r, 4);
        r += __shfl_xor_sync(0xffffffffu, r, 2);
        r += __shfl_xor_sync(0xffffffffu, r, 1);
        if (t == 0) sarr[0] = r;
    }
    __syncthreads();
    float out = sarr[0];
    __syncthreads();
    return out;
}

__global__ void __launch_bounds__(THREADS, 4)
ofp_fused(const float* __restrict__ x, const float* __restrict__ x0,
          float* __restrict__ out)
{
    __shared__ uint32_t sbuf[STAGES * STW];   // 36864 B
    __shared__ float sA[NDIM * NDIM];         // Gram (also finalize staging)
    __shared__ float sx[64];
    __shared__ float sred[64];
    __shared__ int scomm;

    const int t    = threadIdx.x;
    const int lane = t & 31, wid = t >> 5;
    const int l4   = lane & 3, ld4 = lane >> 2;
    const int cta  = blockIdx.x;
    const int b    = cta >> 2, q = cta & 3;
    const int qm   = wid >> 1, qn = wid & 1;  // warp's 32x32 quadrant
    const int m0   = qm * 32 + ld4;
    const int n0f  = qn * 32 + ld4;

    const float* __restrict__ xq =
        x + (size_t)b * (2048 * NDIM) + (size_t)q * (KQ * NDIM);

    const uint32_t sbase = smem_u32(sbuf);

    // Precompute the 13 dst word offsets for this thread (w = t + 128*i -> r*72 + n)
    int doff[13];
    {
        int r = t / NDIM;
        int n = t - NDIM * r;
#pragma unroll
        for (int i = 0; i < 12; i++) {
            doff[i] = r * SROW + n;
            n += 30; r += 2; if (n >= NDIM) { n -= NDIM; r += 1; }   // w += 128
        }
        doff[12] = 31 * SROW + 17 + t;       // tail words 1536..1567 (t<32 only)
    }

    // zero pad words n in [49,64) of all 4 stage buffers (frags read n <= 63)
    for (int i = t; i < STAGES * KCH * 15; i += THREADS) {
        const int bi  = i / (KCH * 15);
        const int rem = i - bi * (KCH * 15);
        const int r   = rem / 15;
        const int n   = NDIM + rem - r * 15;
        sbuf[bi * STW + r * SROW + n] = 0u;
    }
    __syncthreads();                          // pads visible before first frag reads

    float acc[2][4][4];
#pragma unroll
    for (int mt = 0; mt < 2; mt++)
#pragma unroll
        for (int nt = 0; nt < 4; nt++)
#pragma unroll
            for (int ci = 0; ci < 4; ci++) acc[mt][nt][ci] = 0.0f;

    // ---- prologue: issue stages 0..2 ----
#pragma unroll
    for (int s = 0; s < STAGES - 1; s++) {
        const uint32_t dstb = sbase + (uint32_t)(s * STW * 4);
        const float* src = xq + (size_t)s * CHW;
#pragma unroll
        for (int i = 0; i < 12; i++)
            CP_ASYNC4(dstb + 4u * doff[i], src + t + i * THREADS);
        if (t < 32)
            CP_ASYNC4(dstb + 4u * doff[12], src + 1536 + t);
        CP_COMMIT();
    }

    // ---- main loop: 16 stages, 3 in flight ----
    for (int ch = 0; ch < NST; ch++) {
        CP_WAIT(2);                           // stage ch complete
        __syncthreads();

        const uint32_t* bc = sbuf + (ch & (STAGES - 1)) * STW;
#pragma unroll
        for (int kb = 0; kb < 4; kb++) {      // 4 k8 steps
            const uint32_t* lo = bc + (kb * 8 + l4) * SROW;
            const uint32_t* hi = lo + 4 * SROW;
            uint32_t b0[4], b1[4];
#pragma unroll
            for (int nt = 0; nt < 4; nt++) {
                b0[nt] = lo[n0f + nt * 8];
                b1[nt] = hi[n0f + nt * 8];
            }
#pragma unroll
            for (int mt = 0; mt < 2; mt++) {
                const uint32_t a0 = lo[m0 + mt * 16];
                const uint32_t a1 = lo[m0 + mt * 16 + 8];
                const uint32_t a2 = hi[m0 + mt * 16];
                const uint32_t a3 = hi[m0 + mt * 16 + 8];
#pragma unroll
                for (int nt = 0; nt < 4; nt++)
                    mma8(acc[mt][nt], a0, a1, a2, a3, b0[nt], b1[nt]);
            }
        }
        __syncthreads();                      // all warps done reading buf before refill

        if (ch + STAGES - 1 < NST) {
            const int s = ch + STAGES - 1;
            const uint32_t dstb = sbase + (uint32_t)((s & (STAGES - 1)) * STW * 4);
            const float* src = xq + (size_t)s * CHW;
#pragma unroll
            for (int i = 0; i < 12; i++)
                CP_ASYNC4(dstb + 4u * doff[i], src + t + i * THREADS);
            if (t < 32)
                CP_ASYNC4(dstb + 4u * doff[12], src + 1536 + t);
            CP_COMMIT();
        }
    }

    // ---- write 49x49 partial Gram ----
    {
        float* __restrict__ gp = g_partial[cta];
#pragma unroll
        for (int mt = 0; mt < 2; mt++)
#pragma unroll
            for (int nt = 0; nt < 4; nt++) {
                const int rr = qm * 32 + mt * 16 + ld4;
                const int cc = qn * 32 + nt * 8 + 2 * l4;
                const float* a = acc[mt][nt];
                if (rr < NDIM) {
                    if (cc < NDIM)     gp[rr * NDIM + cc]     = a[0];
                    if (cc + 1 < NDIM) gp[rr * NDIM + cc + 1] = a[1];
                }
                if (rr + 8 < NDIM) {
                    if (cc < NDIM)     gp[(rr + 8) * NDIM + cc]     = a[2];
                    if (cc + 1 < NDIM) gp[(rr + 8) * NDIM + cc + 1] = a[3];
                }
            }
    }
    __syncthreads();
    __threadfence();
    if (t == 0) scomm = atomicAdd(&g_cnt[b], 1);
    __syncthreads();
    if (scomm != NQ - 1) return;              // not the last partial of this batch

    // ================= last arriver: power iteration for batch b =================
    __threadfence();
    {
        const float* __restrict__ p0 = g_partial[(b << 2) + 0];
        const float* __restrict__ p1 = g_partial[(b << 2) + 1];
        const float* __restrict__ p2 = g_partial[(b << 2) + 2];
        const float* __restrict__ p3 = g_partial[(b << 2) + 3];
        for (int i = t; i < NDIM * NDIM; i += THREADS)
            sA[i] = (__ldcg(p0 + i) + __ldcg(p1 + i)) +
                    (__ldcg(p2 + i) + __ldcg(p3 + i));
    }
    if (t < NDIM) sx[t] = x0[b * NDIM + t];
    __syncthreads();

    // PI-1: largest eigenvalue of ATA
    for (int it = 0; it < 9; it++) {
        float y = 0.0f;
        if (t < NDIM) {
            const float* __restrict__ rA = &sA[t * NDIM];
#pragma unroll
            for (int m = 0; m < NDIM; m++) y = fmaf(rA[m], sx[m], y);
        }
        const float n2  = reduce49(y * y, t, sred);
        const float nrm = fmaxf(sqrtf(n2), EPSV);
        if (t < NDIM) sx[t] = y / nrm;
        __syncthreads();
    }
    float y = 0.0f, xv = 0.0f;
    if (t < NDIM) {
        xv = sx[t];
        const float* __restrict__ rA = &sA[t * NDIM];
#pragma unroll
        for (int m = 0; m < NDIM; m++) y = fmaf(rA[m], sx[m], y);
    }
    float num = reduce49(y * xv, t, sred);
    float den = reduce49(xv * xv, t, sred);
    const float largest = num / den;

    // PI-2 on (ATA - largest*I), warm-started from x1
    for (int it = 0; it < 9; it++) {
        float ys = 0.0f;
        if (t < NDIM) {
            const float* __restrict__ rA = &sA[t * NDIM];
#pragma unroll
            for (int m = 0; m < NDIM; m++) ys = fmaf(rA[m], sx[m], ys);
            ys -= largest * sx[t];
        }
        const float n2  = reduce49(ys * ys, t, sred);
        const float nrm = fmaxf(sqrtf(n2), EPSV);
        if (t < NDIM) sx[t] = ys / nrm;
        __syncthreads();
    }
    y = 0.0f; xv = 0.0f;
    if (t < NDIM) {
        xv = sx[t];
        const float* __restrict__ rA = &sA[t * NDIM];
#pragma unroll
        for (int m = 0; m < NDIM; m++) y = fmaf(rA[m], sx[m], y);
        y -= largest * xv;
    }
    num = reduce49(y * xv, t, sred);
    den = reduce49(xv * xv, t, sred);
    const float smallest = (num / den) + largest;

    if (t == 0) {
        const float r = largest / smallest - 1.0f;
        g_penalty[b] = r * r;                 // BETA = 1
    }
    __threadfence();
    if (t == 0) scomm = atomicAdd(&g_cnt_all, 1);
    __syncthreads();
    if (scomm != BATCH - 1) return;           // not the global last batch

    // ================= global last arriver: deterministic finalize =================
    __threadfence();
    sA[t] = __ldcg(&g_penalty[t]) + __ldcg(&g_penalty[t + 128]);
    __syncthreads();
#pragma unroll
    for (int off = 64; off > 0; off >>= 1) {
        if (t < off) sA[t] += sA[t + off];
        __syncthreads();
    }
    if (t == 0) out[0] = sA[0] * (1.0f / (float)BATCH);

    // reset counters for the next graph replay
    g_cnt[t] = 0;
    g_cnt[t + 128] = 0;
    if (t == 0) g_cnt_all = 0;
}

extern "C" void kernel_launch(void* const* d_in, const int* in_sizes, int n_in,
                              void* d_out, int out_size) {
    const float* x  = (const float*)d_in[0];   // [256, 2048, 7, 7]
    const float* x0 = (const float*)d_in[1];   // [256, 49, 1]
    float* out = (float*)d_out;

    ofp_fused<<<NCTA, THREADS>>>(x, x0, out);
}

// round 11
// speedup vs baseline: 1.0131x; 1.0096x over previous
#include <cuda_runtime.h>
#include <cstdint>

// Fixed problem: x [256,2048,7,7] fp32, x0 [256,49,1] fp32, out scalar fp32
#define BATCH   256
#define NQ      8                     // K-split partials per batch
#define NCTA    (BATCH * NQ)          // 2048
#define KQ      256                   // channels per CTA
#define KCH     64                    // channels per chunk
#define NCH     (KQ / KCH)            // 4
#define NDIM    49
#define PAIRS   32                    // KCH/2 packed k-pair rows per chunk
#define SROW    72                    // f16x2 words per row -> conflict-free frags
#define BUFW    (PAIRS * SROW)        // 2304 words per buffer
#define THREADS 128
#define EPSV    1e-12f

__device__ float g_partial[NCTA][NDIM * NDIM];   // ~19.7 MB scratch
__device__ float g_penalty[BATCH];
__device__ int   g_cnt[BATCH];        // zero-init; reset each run
__device__ int   g_cnt_all;

// pack two fp32 channel values into f16x2 (hi = k odd, lo = k even)
static __device__ __forceinline__ uint32_t pack_h2(float k_odd, float k_even) {
    uint32_t d;
    asm("cvt.rn.f16x2.f32 %0, %1, %2;" : "=r"(d) : "f"(k_odd), "f"(k_even));
    return d;
}

// m16n8k16 f16 mma, fp32 accumulate (sm_80 PTX, valid on base sm_103)
static __device__ __forceinline__ void mma16(float* c,
    uint32_t a0, uint32_t a1, uint32_t a2, uint32_t a3,
    uint32_t b0, uint32_t b1)
{
    asm("mma.sync.aligned.m16n8k16.row.col.f32.f16.f16.f32 "
        "{%0,%1,%2,%3}, {%4,%5,%6,%7}, {%8,%9}, {%0,%1,%2,%3};"
        : "+f"(c[0]), "+f"(c[1]), "+f"(c[2]), "+f"(c[3])
        : "r"(a0), "r"(a1), "r"(a2), "r"(a3), "r"(b0), "r"(b1));
}

// Block-wide sum over first 49 lanes' values (all 128 threads call).
static __device__ __forceinline__ float reduce49(float v, int t, float* sarr) {
    if (t < 64) sarr[t] = (t < NDIM) ? v : 0.0f;
    __syncthreads();
    if (t < 32) {
        float r = sarr[t] + sarr[t + 32];
        r += __shfl_xor_sync(0xffffffffu, r, 16);
        r += __shfl_xor_sync(0xffffffffu, r, 8);
        r += __shfl_xor_sync(0xffffffffu, r, 4);
        r += __shfl_xor_sync(0xffffffffu, r, 2);
        r += __shfl_xor_sync(0xffffffffu, r, 1);
        if (t == 0) sarr[0] = r;
    }
    __syncthreads();
    float out = sarr[0];
    __syncthreads();
    return out;
}

// load + pack one 64-channel chunk: word w (=r*49+n) <- pack(x[2r+1][n], x[2r][n])
static __device__ __forceinline__ void load_pack(const float* __restrict__ src,
                                                 uint32_t* pre, int t) {
#pragma unroll
    for (int i = 0; i < 12; i++) {
        const int w = t + i * THREADS;
        const int r = w / NDIM;
        const int n = w - r * NDIM;
        const float* p = src + (2 * r) * NDIM + n;
        pre[i] = pack_h2(__ldg(p + NDIM), __ldg(p));
    }
    if (t < 32) {                       // tail words 1536..1567
        const float* p = src + 98 * 31 + 17 + t;
        pre[12] = pack_h2(__ldg(p + NDIM), __ldg(p));
    }
}

static __device__ __forceinline__ void store_pack(uint32_t* dst,
                                                  const uint32_t* pre, int t) {
#pragma unroll
    for (int i = 0; i < 12; i++) {
        const int w = t + i * THREADS;
        const int r = w / NDIM;
        const int n = w - r * NDIM;
        dst[r * SROW + n] = pre[i];
    }
    if (t < 32) dst[31 * SROW + 17 + t] = pre[12];
}

__global__ void __launch_bounds__(THREADS, 8)
ofp_fused(const float* __restrict__ x, const float* __restrict__ x0,
          float* __restrict__ out)
{
    __shared__ uint32_t sbuf[2 * BUFW];      // 18432 B; epilogue aliases sA here
    __shared__ float sx[64];
    __shared__ float sred[64];
    __shared__ int scomm;
    float* sA = (float*)sbuf;                // 2401 floats, buffers dead by then

    const int t    = threadIdx.x;
    const int lane = t & 31, wid = t >> 5;
    const int l4   = lane & 3, ld4 = lane >> 2;
    const int cta  = blockIdx.x;
    const int b    = cta >> 3, q = cta & 7;
    const int qm   = wid >> 1, qn = wid & 1; // warp's 32x32 quadrant
    const int m0   = qm * 32 + ld4;
    const int n0   = qn * 32 + ld4;

    const float* __restrict__ xq =
        x + (size_t)b * (2048 * NDIM) + (size_t)q * (KQ * NDIM);

    // zero pad words n in [49,64) of both buffers (frags read n <= 63)
    for (int i = t; i < 2 * PAIRS * 15; i += THREADS) {
        const int bi  = i / (PAIRS * 15);
        const int rem = i - bi * (PAIRS * 15);
        const int r   = rem / 15;
        const int n   = NDIM + rem - r * 15;
        sbuf[bi * BUFW + r * SROW + n] = 0u;
    }

    float acc[2][4][4];
#pragma unroll
    for (int mt = 0; mt < 2; mt++)
#pragma unroll
        for (int nt = 0; nt < 4; nt++)
#pragma unroll
            for (int ci = 0; ci < 4; ci++) acc[mt][nt][ci] = 0.0f;

    // ---- prologue: chunk 0 ----
    uint32_t pre[13];
    load_pack(xq, pre, t);
    store_pack(sbuf, pre, t);
    __syncthreads();

    // ---- main loop: 4 chunks, double-buffered, 1 sync/iter ----
    for (int ch = 0; ch < NCH; ch++) {
        if (ch + 1 < NCH)
            load_pack(xq + (size_t)(ch + 1) * (KCH * NDIM), pre, t);

        const uint32_t* bc = sbuf + (ch & 1) * BUFW;
#pragma unroll
        for (int kb = 0; kb < 4; kb++) {          // 4 k16 steps (8 pair-rows each)
            const uint32_t* lo = bc + (kb * 8 + l4) * SROW;
            const uint32_t* hi = lo + 4 * SROW;
            uint32_t b0[4], b1[4];
#pragma unroll
            for (int nt = 0; nt < 4; nt++) {
                b0[nt] = lo[n0 + nt * 8];
                b1[nt] = hi[n0 + nt * 8];
            }
#pragma unroll
            for (int mt = 0; mt < 2; mt++) {
                const uint32_t a0 = lo[m0 + mt * 16];
                const uint32_t a1 = lo[m0 + mt * 16 + 8];
                const uint32_t a2 = hi[m0 + mt * 16];
                const uint32_t a3 = hi[m0 + mt * 16 + 8];
#pragma unroll
                for (int nt = 0; nt < 4; nt++)
                    mma16(acc[mt][nt], a0, a1, a2, a3, b0[nt], b1[nt]);
            }
        }
        if (ch + 1 < NCH)
            store_pack(sbuf + ((ch + 1) & 1) * BUFW, pre, t);
        __syncthreads();
    }

    // ---- write 49x49 partial Gram ----
    {
        float* __restrict__ gp = g_partial[cta];
#pragma unroll
        for (int mt = 0; mt < 2; mt++)
#pragma unroll
            for (int nt = 0; nt < 4; nt++) {
                const int rr = qm * 32 + mt * 16 + ld4;
                const int cc = qn * 32 + nt * 8 + 2 * l4;
                const float* a = acc[mt][nt];
                if (rr < NDIM) {
                    if (cc < NDIM)     gp[rr * NDIM + cc]     = a[0];
                    if (cc + 1 < NDIM) gp[rr * NDIM + cc + 1] = a[1];
                }
                if (rr + 8 < NDIM) {
                    if (cc < NDIM)     gp[(rr + 8) * NDIM + cc]     = a[2];
                    if (cc + 1 < NDIM) gp[(rr + 8) * NDIM + cc + 1] = a[3];
                }
            }
    }
    __syncthreads();
    __threadfence();
    if (t == 0) scomm = atomicAdd(&g_cnt[b], 1);
    __syncthreads();
    if (scomm != NQ - 1) return;              // not the last partial of this batch

    // ================= last arriver: power iteration for batch b =================
    __threadfence();
    {
        const float* __restrict__ p0 = g_partial[(b << 3) + 0];
        const float* __restrict__ p1 = g_partial[(b << 3) + 1];
        const float* __restrict__ p2 = g_partial[(b << 3) + 2];
        const float* __restrict__ p3 = g_partial[(b << 3) + 3];
        const float* __restrict__ p4 = g_partial[(b << 3) + 4];
        const float* __restrict__ p5 = g_partial[(b << 3) + 5];
        const float* __restrict__ p6 = g_partial[(b << 3) + 6];
        const float* __restrict__ p7 = g_partial[(b << 3) + 7];
        for (int i = t; i < NDIM * NDIM; i += THREADS)
            sA[i] = ((__ldcg(p0 + i) + __ldcg(p1 + i)) +
                     (__ldcg(p2 + i) + __ldcg(p3 + i))) +
                    ((__ldcg(p4 + i) + __ldcg(p5 + i)) +
                     (__ldcg(p6 + i) + __ldcg(p7 + i)));
    }
    if (t < NDIM) sx[t] = x0[b * NDIM + t];
    __syncthreads();

    // PI-1: largest eigenvalue of ATA
    for (int it = 0; it < 9; it++) {
        float y = 0.0f;
        if (t < NDIM) {
            const float* __restrict__ rA = &sA[t * NDIM];
#pragma unroll
            for (int m = 0; m < NDIM; m++) y = fmaf(rA[m], sx[m], y);
        }
        const float n2  = reduce49(y * y, t, sred);
        const float nrm = fmaxf(sqrtf(n2), EPSV);
        if (t < NDIM) sx[t] = y / nrm;
        __syncthreads();
    }
    float y = 0.0f, xv = 0.0f;
    if (t < NDIM) {
        xv = sx[t];
        const float* __restrict__ rA = &sA[t * NDIM];
#pragma unroll
        for (int m = 0; m < NDIM; m++) y = fmaf(rA[m], sx[m], y);
    }
    float num = reduce49(y * xv, t, sred);
    float den = reduce49(xv * xv, t, sred);
    const float largest = num / den;

    // PI-2 on (ATA - largest*I), warm-started from x1
    for (int it = 0; it < 9; it++) {
        float ys = 0.0f;
        if (t < NDIM) {
            const float* __restrict__ rA = &sA[t * NDIM];
#pragma unroll
            for (int m = 0; m < NDIM; m++) ys = fmaf(rA[m], sx[m], ys);
            ys -= largest * sx[t];
        }
        const float n2  = reduce49(ys * ys, t, sred);
        const float nrm = fmaxf(sqrtf(n2), EPSV);
        if (t < NDIM) sx[t] = ys / nrm;
        __syncthreads();
    }
    y = 0.0f; xv = 0.0f;
    if (t < NDIM) {
        xv = sx[t];
        const float* __restrict__ rA = &sA[t * NDIM];
#pragma unroll
        for (int m = 0; m < NDIM; m++) y = fmaf(rA[m], sx[m], y);
        y -= largest * xv;
    }
    num = reduce49(y * xv, t, sred);
    den = reduce49(xv * xv, t, sred);
    const float smallest = (num / den) + largest;

    if (t == 0) {
        const float r = largest / smallest - 1.0f;
        g_penalty[b] = r * r;                 // BETA = 1
    }
    __threadfence();
    if (t == 0) scomm = atomicAdd(&g_cnt_all, 1);
    __syncthreads();
    if (scomm != BATCH - 1) return;           // not the global last batch

    // ================= global last arriver: deterministic finalize =================
    __threadfence();
    sA[t] = __ldcg(&g_penalty[t]) + __ldcg(&g_penalty[t + 128]);
    __syncthreads();
#pragma unroll
    for (int off = 64; off > 0; off >>= 1) {
        if (t < off) sA[t] += sA[t + off];
        __syncthreads();
    }
    if (t == 0) out[0] = sA[0] * (1.0f / (float)BATCH);

    // reset counters for the next graph replay
    g_cnt[t] = 0;
    g_cnt[t + 128] = 0;
    if (t == 0) g_cnt_all = 0;
}

extern "C" void kernel_launch(void* const* d_in, const int* in_sizes, int n_in,
                              void* d_out, int out_size) {
    const float* x  = (const float*)d_in[0];   // [256, 2048, 7, 7]
    const float* x0 = (const float*)d_in[1];   // [256, 49, 1]
    float* out = (float*)d_out;

    ofp_fused<<<NCTA, THREADS>>>(x, x0, out);
}